// round 11
// baseline (speedup 1.0000x reference)
#include <cuda_runtime.h>
#include <cuda_bf16.h>

// T=4096, B=512, n=32, deg=3. Sequential nonlinear RNN over T.
//
// R11 = R10 (PASS 552us, rel_err 1.6369585e-4, proven FMA-ISSUE-BOUND:
// 127 fma-pipe ops x rt2 = 254 cyc = measured 255 cyc/step) with ONE change:
//   v-updates packed 2 states per instruction via f32x2 (mul/fma.rn.f32x2 =
//   two independent IEEE-RN scalar ops => bit-identical rounding), exactly
//   replicating nvcc's scalar contraction pattern:
//       v = fma(h, b, fma(dec, v, mul(cur, a)))
// Serial natural-order sum, poly, select, lean df tanh: VERBATIM from R10.
// Validation: rel_err must return EXACTLY 0.0001636959.

typedef unsigned long long ull;

__device__ __forceinline__ ull pack2(float x, float y) {
    ull r; asm("mov.b64 %0, {%1, %2};" : "=l"(r) : "f"(x), "f"(y)); return r;
}
__device__ __forceinline__ float2 unpack2(ull v) {
    float2 f; asm("mov.b64 {%0, %1}, %2;" : "=f"(f.x), "=f"(f.y) : "l"(v)); return f;
}
__device__ __forceinline__ ull fma2(ull a, ull b, ull c) {
    ull d; asm("fma.rn.f32x2 %0, %1, %2, %3;" : "=l"(d) : "l"(a), "l"(b), "l"(c)); return d;
}
__device__ __forceinline__ ull mul2(ull a, ull b) {
    ull d; asm("mul.rn.f32x2 %0, %1, %2;" : "=l"(d) : "l"(a), "l"(b)); return d;
}

static constexpr int BATCH  = 512;
static constexpr int NSTATE = 32;
static constexpr int NV2    = NSTATE / 2;  // 16 packed pairs per thread
static constexpr int PF     = 8;           // ring depth == unroll factor

// Lean double-float tanh for x in (0, 9.2]. (verbatim from R10)
__device__ __forceinline__ float tanh_df_lean(float x) {
    const float t  = 2.0f * x;
    const float kf = rintf(t * 1.4426950408889634f);
    const int   ki = (int)kf;

    const float L_h = 0.693147182464599609375f;
    const float L_l = -1.9046542996577634e-9f;
    const float ph = kf * L_h;
    const float pe = fmaf(kf, L_h, -ph);
    const float d  = t - ph;
    const float rh = d - pe;
    const float bb = rh - d;
    const float er = (d - (rh - bb)) + (-pe - bb);
    const float rl = er - kf * L_l;

    const float r2h = rh * rh;
    float r2l = fmaf(rh, rh, -r2h);
    r2l = fmaf(2.0f * rh, rl, r2l);

    float C = fmaf(rh, 2.4801587302e-5f, 1.9841269841e-4f);
    C = fmaf(rh, C, 1.3888888889e-3f);
    C = fmaf(rh, C, 8.3333333333e-3f);
    C = fmaf(rh, C, 4.1666666667e-2f);
    C = fmaf(rh, C, 1.6666666667e-1f);
    const float cub = (r2h * rh) * C;

    const float q  = 0.5f * r2h;
    float mh = rh + q;
    float ml = (rh - mh) + q;
    ml = ml + (cub + (rl + 0.5f * r2l));
    { const float s = mh + ml; ml = ml - (s - mh); mh = s; }

    const float pk = __int_as_float((ki + 127) << 23);
    const float ah = pk * mh;
    const float al = fmaf(pk, ml, fmaf(pk, mh, -ah));

    const float n1 = pk - 1.0f;
    const float nd = n1 - pk;
    const float ne = (pk - (n1 - nd)) + (-1.0f - nd);
    const float nh = n1 + ah;
    const float tb1 = nh - n1;
    const float nl = ((n1 - (nh - tb1)) + (ah - tb1)) + ne + al;

    const float d1 = pk + 1.0f;
    const float dd = d1 - pk;
    const float de = (pk - (d1 - dd)) + (1.0f - dd);
    const float dh = d1 + ah;
    const float tb2 = dh - d1;
    const float dl = ((d1 - (dh - tb2)) + (ah - tb2)) + de + al;

    float rcp;
    asm("rcp.approx.f32 %0, %1;" : "=f"(rcp) : "f"(dh));
    const float q0 = nh * rcp;
    const float e1 = fmaf(-q0, dh, nh);
    const float resid = e1 + fmaf(-q0, dl, nl);
    return fmaf(resid, rcp, q0);
}

__global__ void __launch_bounds__(32, 1)
rnn_firing_rate_r11(const float* __restrict__ currents,   // [T, B]
                    const float* __restrict__ a_vec,      // [n]
                    const float* __restrict__ b_vec,      // [n]
                    const float* __restrict__ ds,         // [n]
                    const float* __restrict__ poly_coeff, // [4]
                    const float* __restrict__ g_b,        // [1]
                    float* __restrict__ out,              // [T, B]
                    int T)
{
    const int batch = blockIdx.x * 32 + threadIdx.x;

    // packed per-thread constants/state: pair j = states (2j, 2j+1)
    ull av2[NV2], bv2[NV2], dec2[NV2], v2[NV2];
    #pragma unroll
    for (int j = 0; j < NV2; ++j) {
        const int k = 2 * j;
        av2[j]  = pack2(a_vec[k], a_vec[k + 1]);
        bv2[j]  = pack2(b_vec[k], b_vec[k + 1]);
        dec2[j] = pack2(1.0f - ds[k], 1.0f - ds[k + 1]);
        v2[j]   = pack2(0.0f, 0.0f);
    }
    const float c0 = poly_coeff[0] * poly_coeff[0];
    const float c1 = poly_coeff[1] * poly_coeff[1];
    const float c2 = poly_coeff[2] * poly_coeff[2];
    const float c3 = poly_coeff[3] * poly_coeff[3];
    const float gbv = g_b[0];

    // current prefetch ring — static indices after unroll => registers
    float cbuf[PF];
    #pragma unroll
    for (int i = 0; i < PF; ++i)
        cbuf[i] = (i < T) ? currents[i * BATCH + batch] : 0.0f;

    const float* cptr = currents + (size_t)PF * BATCH + batch;
    float*       optr = out + batch;

    float fs = 0.0f;

    for (int tblk = 0; tblk < T; tblk += PF) {
        #pragma unroll
        for (int u = 0; u < PF; ++u) {
            const int t = tblk + u;
            const float cur = cbuf[u];
            if (t + PF < T) cbuf[u] = cptr[u * BATCH];

            const float h = 1000.0f * fs;   // feedback from PREVIOUS step

            const ull cur2 = pack2(cur, cur);
            const ull h2   = pack2(h, h);

            // v = fma(h, b, fma(dec, v, mul(cur, a))) — packed, two IEEE-RN
            // scalar ops per instruction, bit-identical to R10's scalar
            // contraction. Sum in natural order k=0..31, serial (pinned).
            float s = 0.0f;
            #pragma unroll
            for (int j = 0; j < NV2; ++j) {
                const ull m = mul2(cur2, av2[j]);       // round(cur*a)
                const ull w = fma2(dec2[j], v2[j], m);  // round(dec*v + m)
                v2[j] = fma2(h2, bv2[j], w);            // round(h*b + w)
                const float2 p = unpack2(v2[j]);
                s += p.x;                               // += v[2j]
                s += p.y;                               // += v[2j+1]
            }

            // z = mean(v) - g_b ; poly = c0 + c1 z + c2 z^2 + c3 z^3 (verbatim)
            const float z  = s * (1.0f / 32.0f) - gbv;
            const float z2 = z * z;
            const float z3 = z2 * z;
            const float poly = c0 + c1 * z + c2 * z2 + c3 * z3;

            // fs = relu(100 * tanh(poly)) with exact clip zones (verbatim)
            const bool mid = (poly > 0.0f) && (poly <= 9.2f);
            float fs_mid = 0.0f;
            if (__ballot_sync(0xFFFFFFFFu, mid)) {
                const float th = tanh_df_lean(poly);
                fs_mid = fmaxf(100.0f * th, 0.0f);
            }
            fs = (poly <= 0.0f) ? 0.0f : ((poly > 9.2f) ? 100.0f : fs_mid);

            *optr = fs;
            optr += BATCH;
        }
        cptr += PF * BATCH;
    }
}

extern "C" void kernel_launch(void* const* d_in, const int* in_sizes, int n_in,
                              void* d_out, int out_size)
{
    const float* currents   = (const float*)d_in[0];  // [T*B]
    const float* a_vec      = (const float*)d_in[1];  // [32]
    const float* b_vec      = (const float*)d_in[2];  // [32]
    const float* ds         = (const float*)d_in[3];  // [32]
    const float* poly_coeff = (const float*)d_in[4];  // [4]
    const float* g_b        = (const float*)d_in[5];  // [1]
    float* out = (float*)d_out;

    const int T = in_sizes[0] / BATCH;                // 4096

    rnn_firing_rate_r11<<<BATCH / 32, 32>>>(currents, a_vec, b_vec, ds,
                                            poly_coeff, g_b, out, T);
}